// round 14
// baseline (speedup 1.0000x reference)
#include <cuda_runtime.h>

#define B  32
#define L  1024
#define D  512
#define NN 512

#define GRID 1024

// 8 partial-sum planes of sum_l(i - j) over L-eighths: [8][B][D]
__device__ float g_part[8 * B * D];
// reduced mean-diff md[b][d]
__device__ float g_md[B * D];
// grid-barrier ticket counter (zero-init; epoch math => graph-replay-safe)
__device__ unsigned int g_bar;
// DCE-defeating sink for the W prefetch
__device__ float g_sink;

// Epoch grid barrier: each launch passes 2 barriers * 1024 arrivals = 2048,
// a multiple of 1024, so the counter needs no reset across graph replays.
__device__ __forceinline__ void grid_barrier(int tid)
{
    __threadfence();                       // release my prior global writes
    __syncthreads();
    if (tid == 0) {
        unsigned int ticket = atomicAdd(&g_bar, 1u);
        unsigned int target = (ticket / GRID + 1u) * GRID;
        while (*(volatile unsigned int*)&g_bar < target) { }
        __threadfence();                   // acquire others' writes
    }
    __syncthreads();
}

// ---------------------------------------------------------------------------
// ONE fused kernel, 1024 blocks x 256 threads, ALL blocks resident
// (launch_bounds(256,8): 8 blocks/SM x 148 SMs = 1184 slots >= 1024).
//
// Phase 1  (~22.9us): part[lo][b][d] = sum_{l in eighth lo}(i-j), the 128MB
//          HBM stream. Full-warp 512B LDG.128 rows, __ldcs so W stays in L2.
//          Side job: prefetch W (1 MB) into L2 for phase B.
// Barrier 1.
// Phase A  (~0.2us): md[b][d] = (1/L) * sum_pl part[pl][b][d]; 16 elems/block.
// Barrier 2.
// Phase B  (~2us): u[b][n] = sum_d md[b][d]*W[d][n];
//          out = 0.5*(relu(u+bias)+relu(bias-u)).
//          Block = 2 batches x 8 n-cols x 512 d  (bg=blk>>6, nt=blk&63).
//          W L2 traffic 16MB, md 4MB — covered by 262K warm threads.
// ---------------------------------------------------------------------------
__global__ void __launch_bounds__(256, 8) fused_kernel(
    const float* __restrict__ gi, const float* __restrict__ gj,
    const float* __restrict__ W,  const float* __restrict__ bias,
    float* __restrict__ out)
{
    const int blk = blockIdx.x;
    const int tid = threadIdx.x;

    __shared__ float4 s[256];            // phase-1 reduce
    __shared__ float  smd[2][D];         // phase-B md stage
    __shared__ float  su[2][256];        // phase-B partials

    // ================= Phase 1: streaming mean-diff =================
    {
        const int b   = blk >> 5;        // batch
        const int r   = blk & 31;
        const int dt  = r >> 3;          // 128-float d tile (4 per D)
        const int lo  = r & 7;           // L eighth
        const int dq  = tid & 31;        // float4 within tile
        const int lg  = tid >> 5;        // l-group (8 x 16 rows)

        // W prefetch: 1024 blocks x 64 float4 = 1 MB into L2
        if (tid < 64) {
            float4 w = __ldcg(((const float4*)W) + blk * 64 + tid);
            float t = w.x + w.y + w.z + w.w;
            if (__float_as_int(t) == 0x7f800001)  // never true in practice
                g_sink = t;
        }

        const int rowq = D / 4;
        const float4* pi = (const float4*)(gi + (size_t)b * L * D) + dt * 32 + dq;
        const float4* pj = (const float4*)(gj + (size_t)b * L * D) + dt * 32 + dq;

        const int l0 = lo * 128 + lg * 16;
        float4 acc = make_float4(0.f, 0.f, 0.f, 0.f);
        #pragma unroll
        for (int rr = 0; rr < 16; rr++) {
            size_t off = (size_t)(l0 + rr) * rowq;
            float4 a = __ldcs(pi + off);
            float4 c = __ldcs(pj + off);
            acc.x += a.x - c.x;
            acc.y += a.y - c.y;
            acc.z += a.z - c.z;
            acc.w += a.w - c.w;
        }

        s[tid] = acc;
        __syncthreads();

        #pragma unroll
        for (int stride = 128; stride >= 32; stride >>= 1) {
            if (tid < stride) {
                float4 o = s[tid + stride];
                s[tid].x += o.x; s[tid].y += o.y; s[tid].z += o.z; s[tid].w += o.w;
            }
            __syncthreads();
        }

        if (tid < 32)
            ((float4*)(g_part + lo * B * D + b * D + dt * 128))[tid] = s[tid];
    }

    grid_barrier(tid);

    // ================= Phase A: plane reduction =================
    if (tid < 16) {
        const int idx = blk * 16 + tid;          // idx = b*D + d
        float v = 0.f;
        #pragma unroll
        for (int pl = 0; pl < 8; pl++)
            v += g_part[pl * B * D + idx];
        g_md[idx] = v * (1.0f / (float)L);
    }

    grid_barrier(tid);

    // ================= Phase B: GEMV + combine =================
    {
        const int bg = blk >> 6;         // 16 batch pairs
        const int nt = blk & 63;         // 8-wide n tile
        const int b0 = bg * 2;

        // stage md for 2 batches: 1024 floats = 256 float4, coalesced
        ((float4*)&smd[0][0])[tid] = ((const float4*)(g_md + b0 * D))[tid];
        __syncthreads();

        const int nloc = tid & 7;
        const int dg   = tid >> 3;       // 32 d-groups of 16 rows
        const int n    = nt * 8 + nloc;
        const float* Wp = W + (size_t)(dg * 16) * NN + n;

        float u0 = 0.f, u1 = 0.f;
        #pragma unroll
        for (int d = 0; d < 16; d++) {
            float w = __ldg(Wp + (size_t)d * NN);
            const int di = dg * 16 + d;
            u0 = fmaf(smd[0][di], w, u0);
            u1 = fmaf(smd[1][di], w, u1);
        }

        su[0][tid] = u0;
        su[1][tid] = u1;
        __syncthreads();

        // 16 outputs (2 batches x 8 n), each a 32-way partial sum
        if (tid < 16) {
            const int bb = tid >> 3;
            const int nn = tid & 7;
            float t = 0.f;
            #pragma unroll
            for (int g = 0; g < 32; g++)
                t += su[bb][g * 8 + nn];
            float bv = bias[nt * 8 + nn];
            out[(b0 + bb) * NN + nt * 8 + nn] =
                0.5f * (fmaxf(t + bv, 0.f) + fmaxf(bv - t, 0.f));
        }
    }
}

extern "C" void kernel_launch(void* const* d_in, const int* in_sizes, int n_in,
                              void* d_out, int out_size)
{
    const float* gi   = (const float*)d_in[0];   // i     [B, L, D]
    const float* gj   = (const float*)d_in[1];   // j     [B, L, D]
    const float* W    = (const float*)d_in[2];   // W_agg [D, NN]
    const float* bias = (const float*)d_in[3];   // b_agg [NN]
    float* out = (float*)d_out;                  // [B, NN]

    fused_kernel<<<GRID, 256>>>(gi, gj, W, bias, out);
}

// round 15
// speedup vs baseline: 1.1360x; 1.1360x over previous
#include <cuda_runtime.h>

#define B  32
#define L  1024
#define D  512
#define NN 512

// 8 partial-sum planes of sum_l(i - j) over L-eighths: [8][B][D]
__device__ float g_part[8 * B * D];
// DCE-defeating sink for the W prefetch
__device__ float g_sink;

// ---------------------------------------------------------------------------
// Kernel 1 (unchanged — measured ~22.9us, ~5.6-6.4 TB/s):
// part[lo][b][d] = sum_{l in eighth lo} (i[b,l,d] - j[b,l,d])
// 1024 blocks x 256 thr, all resident (8 blocks/SM, <=32 regs).
// Full-warp 512B LDG.128 rows, __ldcs streaming so W stays in L2.
// Side job: prefetch W (1 MB) into L2 for kernel 2.
// ---------------------------------------------------------------------------
__global__ void __launch_bounds__(256, 8) mean_diff_kernel(
    const float* __restrict__ gi, const float* __restrict__ gj,
    const float* __restrict__ W)
{
    const int blk = blockIdx.x;
    const int b   = blk >> 5;         // batch
    const int r   = blk & 31;
    const int dt  = r >> 3;           // 128-float d tile (4 per D)
    const int lo  = r & 7;            // L eighth
    const int tid = threadIdx.x;
    const int dq  = tid & 31;         // float4 within 128-float tile
    const int lg  = tid >> 5;         // l-group (8 groups x 16 rows)

    // --- W prefetch: 1024 blocks x 64 float4 = 1 MB into L2 ---
    if (tid < 64) {
        float4 w = __ldcg(((const float4*)W) + blk * 64 + tid);
        float t = w.x + w.y + w.z + w.w;
        if (__float_as_int(t) == 0x7f800001)  // never true in practice
            g_sink = t;
    }

    const int rowq = D / 4;           // 128 float4 per row
    const float4* pi = (const float4*)(gi + (size_t)b * L * D) + dt * 32 + dq;
    const float4* pj = (const float4*)(gj + (size_t)b * L * D) + dt * 32 + dq;

    const int l0 = lo * 128 + lg * 16;
    float4 acc = make_float4(0.f, 0.f, 0.f, 0.f);
    #pragma unroll
    for (int rr = 0; rr < 16; rr++) {
        size_t off = (size_t)(l0 + rr) * rowq;
        float4 a = __ldcs(pi + off);
        float4 c = __ldcs(pj + off);
        acc.x += a.x - c.x;
        acc.y += a.y - c.y;
        acc.z += a.z - c.z;
        acc.w += a.w - c.w;
    }

    __shared__ float4 s[256];
    s[tid] = acc;
    __syncthreads();

    #pragma unroll
    for (int stride = 128; stride >= 32; stride >>= 1) {
        if (tid < stride) {
            float4 o = s[tid + stride];
            s[tid].x += o.x; s[tid].y += o.y; s[tid].z += o.z; s[tid].w += o.w;
        }
        __syncthreads();
    }

    if (tid < 32)
        ((float4*)(g_part + lo * B * D + b * D + dt * 128))[tid] = s[tid];
}

// ---------------------------------------------------------------------------
// Kernel 2: md[b,d] = (1/L) * sum_lo part[lo][b][d]
//           u[b,n]  = sum_d md[b,d] * W[d,n]
//           out[b,n] = 0.5*(relu(u + bias[n]) + relu(bias[n] - u))
// Grid: 16 batch-pairs * 8 n-tiles(64 floats) = 128 blocks (ONE exact wave)
// x 1024 threads (32 warps/SM — 2x R11's latency coverage).
// Prologue: plane-reduce md for 2 batches (8 coalesced L2-hot loads/thread).
// Main: q = tid&15 (float4 col), dg = tid>>4 (64 d-groups of 8 rows).
// Per thread: 8 independent float4 W loads (ALL in flight) + 64 FMAs,
// each W element reused for 2 batches. Per SM: 32 warps x 8 LDG.128 =
// 256 in-flight loads -> L2 latency fully covered.
// ---------------------------------------------------------------------------
__global__ void __launch_bounds__(1024) gemv_combine_kernel(
    const float* __restrict__ W, const float* __restrict__ bias,
    float* __restrict__ out)
{
    const int blk = blockIdx.x;
    const int bp  = blk >> 3;         // batch pair (16)
    const int nt  = blk & 7;          // 64-float n tile (8)
    const int b0  = bp * 2;
    const int tid = threadIdx.x;

    __shared__ float smd[2][D];
    // plane-reduce md for this block's 2 batches (1024 threads = 1024 elems)
    {
        const int bb = tid >> 9;      // 0..1
        const int d  = tid & 511;
        const float* p = g_part + (b0 + bb) * D + d;
        float v = 0.f;
        #pragma unroll
        for (int pl = 0; pl < 8; pl++)
            v += p[pl * B * D];
        smd[bb][d] = v * (1.0f / (float)L);
    }
    __syncthreads();

    const int q  = tid & 15;          // float4 column within 64-float tile
    const int dg = tid >> 4;          // d-group 0..63 (8 rows each)
    const float4* W4 = (const float4*)W + (size_t)(dg * 8) * (NN / 4) + nt * 16 + q;

    float4 u0 = make_float4(0.f, 0.f, 0.f, 0.f);
    float4 u1 = make_float4(0.f, 0.f, 0.f, 0.f);
    #pragma unroll
    for (int d = 0; d < 8; d++) {
        float4 w = __ldg(W4 + (size_t)d * (NN / 4));
        const int di = dg * 8 + d;
        float m0 = smd[0][di];
        float m1 = smd[1][di];
        u0.x = fmaf(m0, w.x, u0.x);  u0.y = fmaf(m0, w.y, u0.y);
        u0.z = fmaf(m0, w.z, u0.z);  u0.w = fmaf(m0, w.w, u0.w);
        u1.x = fmaf(m1, w.x, u1.x);  u1.y = fmaf(m1, w.y, u1.y);
        u1.z = fmaf(m1, w.z, u1.z);  u1.w = fmaf(m1, w.w, u1.w);
    }

    __shared__ float4 su0[1024];
    __shared__ float4 su1[1024];
    su0[tid] = u0;
    su1[tid] = u1;
    __syncthreads();

    // reduce over the 64 d-groups (stride 16 in tid space)
    #pragma unroll
    for (int stride = 512; stride >= 16; stride >>= 1) {
        if (tid < stride) {
            float4 a = su0[tid + stride];
            su0[tid].x += a.x; su0[tid].y += a.y; su0[tid].z += a.z; su0[tid].w += a.w;
            float4 c = su1[tid + stride];
            su1[tid].x += c.x; su1[tid].y += c.y; su1[tid].z += c.z; su1[tid].w += c.w;
        }
        __syncthreads();
    }

    // 32 outputs lanes: 2 batches x 16 float4
    if (tid < 32) {
        const int bb = tid >> 4;
        const int qq = tid & 15;
        float4 t  = bb ? su1[qq] : su0[qq];
        float4 bv = ((const float4*)bias)[nt * 16 + qq];
        float4 r;
        r.x = 0.5f * (fmaxf(t.x + bv.x, 0.f) + fmaxf(bv.x - t.x, 0.f));
        r.y = 0.5f * (fmaxf(t.y + bv.y, 0.f) + fmaxf(bv.y - t.y, 0.f));
        r.z = 0.5f * (fmaxf(t.z + bv.z, 0.f) + fmaxf(bv.z - t.z, 0.f));
        r.w = 0.5f * (fmaxf(t.w + bv.w, 0.f) + fmaxf(bv.w - t.w, 0.f));
        ((float4*)out)[(b0 + bb) * (NN / 4) + nt * 16 + qq] = r;
    }
}

extern "C" void kernel_launch(void* const* d_in, const int* in_sizes, int n_in,
                              void* d_out, int out_size)
{
    const float* gi   = (const float*)d_in[0];   // i     [B, L, D]
    const float* gj   = (const float*)d_in[1];   // j     [B, L, D]
    const float* W    = (const float*)d_in[2];   // W_agg [D, NN]
    const float* bias = (const float*)d_in[3];   // b_agg [NN]
    float* out = (float*)d_out;                  // [B, NN]

    mean_diff_kernel<<<1024, 256>>>(gi, gj, W);
    gemv_combine_kernel<<<128, 1024>>>(W, bias, out);
}

// round 16
// speedup vs baseline: 1.1525x; 1.0145x over previous
#include <cuda_runtime.h>

#define B  32
#define L  1024
#define D  512
#define NN 512

// 8 partial-sum planes of sum_l(i - j) over L-eighths: [8][B][D]
__device__ float g_part[8 * B * D];
// DCE-defeating sink for the W prefetch
__device__ float g_sink;

// ---------------------------------------------------------------------------
// Kernel 1 (structure unchanged — ~22.9us, ~5.6-6.4 TB/s):
// part[lo][b][d] = sum_{l in eighth lo} (i[b,l,d] - j[b,l,d])
// 1024 blocks x 256 thr, all resident. Full-warp 512B LDG.128 rows, __ldcs
// streaming so W stays in L2. Side job: prefetch W (1 MB) into L2.
// NEW: griddepcontrol.launch_dependents after the streaming loop — lets the
// PDL-attributed gemv kernel launch into SM slots as this grid drains.
// ---------------------------------------------------------------------------
__global__ void __launch_bounds__(256, 8) mean_diff_kernel(
    const float* __restrict__ gi, const float* __restrict__ gj,
    const float* __restrict__ W)
{
    const int blk = blockIdx.x;
    const int b   = blk >> 5;         // batch
    const int r   = blk & 31;
    const int dt  = r >> 3;           // 128-float d tile (4 per D)
    const int lo  = r & 7;            // L eighth
    const int tid = threadIdx.x;
    const int dq  = tid & 31;         // float4 within 128-float tile
    const int lg  = tid >> 5;         // l-group (8 groups x 16 rows)

    // --- W prefetch: 1024 blocks x 64 float4 = 1 MB into L2 ---
    if (tid < 64) {
        float4 w = __ldcg(((const float4*)W) + blk * 64 + tid);
        float t = w.x + w.y + w.z + w.w;
        if (__float_as_int(t) == 0x7f800001)  // never true in practice
            g_sink = t;
    }

    const int rowq = D / 4;           // 128 float4 per row
    const float4* pi = (const float4*)(gi + (size_t)b * L * D) + dt * 32 + dq;
    const float4* pj = (const float4*)(gj + (size_t)b * L * D) + dt * 32 + dq;

    const int l0 = lo * 128 + lg * 16;
    float4 acc = make_float4(0.f, 0.f, 0.f, 0.f);
    #pragma unroll
    for (int rr = 0; rr < 16; rr++) {
        size_t off = (size_t)(l0 + rr) * rowq;
        float4 a = __ldcs(pi + off);
        float4 c = __ldcs(pj + off);
        acc.x += a.x - c.x;
        acc.y += a.y - c.y;
        acc.z += a.z - c.z;
        acc.w += a.w - c.w;
    }

    // allow dependent (PDL) kernel to begin launching as slots free up
    asm volatile("griddepcontrol.launch_dependents;");

    __shared__ float4 s[256];
    s[tid] = acc;
    __syncthreads();

    #pragma unroll
    for (int stride = 128; stride >= 32; stride >>= 1) {
        if (tid < stride) {
            float4 o = s[tid + stride];
            s[tid].x += o.x; s[tid].y += o.y; s[tid].z += o.z; s[tid].w += o.w;
        }
        __syncthreads();
    }

    if (tid < 32)
        ((float4*)(g_part + lo * B * D + b * D + dt * 128))[tid] = s[tid];
}

// ---------------------------------------------------------------------------
// Kernel 2 (R6's best 6.27us structure + PDL W-hoist):
// Grid: 16 batch-pairs * 16 n-tiles(32 wide) = 256 blocks x 512 threads.
// PRE-WAIT: all 32 W values loaded into registers (independent of K1 output;
//           latency overlaps K1's drain).
// griddepcontrol.wait  -> guarantees all g_part writes visible.
// POST-WAIT: plane-reduce md (8 L2 loads), 64 FMAs from registers, smem
//            reduce, combine with bias. ~1-1.5us of serial work.
// ---------------------------------------------------------------------------
__global__ void __launch_bounds__(512) gemv_combine_kernel(
    const float* __restrict__ W, const float* __restrict__ bias,
    float* __restrict__ out)
{
    const int blk  = blockIdx.x;
    const int bg   = blk >> 4;        // batch pair (2 batches)
    const int nt   = blk & 15;        // 32-wide n tile
    const int b0   = bg * 2;
    const int tid  = threadIdx.x;
    const int nloc = tid & 31;
    const int dg   = tid >> 5;        // d-group 0..15 (32 rows each)

    // ---- pre-wait: hoist all W loads (independent of kernel 1) ----
    const int n = nt * 32 + nloc;
    const float* Wp = W + (size_t)(dg * 32) * NN + n;
    float w[32];
    #pragma unroll
    for (int d = 0; d < 32; d++)
        w[d] = __ldg(Wp + (size_t)d * NN);

    // ---- wait for kernel 1 completion (all g_part writes visible) ----
    asm volatile("griddepcontrol.wait;" ::: "memory");

    __shared__ float smd[2][D];
    {
        const float inv = 1.0f / (float)L;
        #pragma unroll
        for (int bb = 0; bb < 2; bb++) {
            const float* p = g_part + (b0 + bb) * D + tid;
            float v = 0.f;
            #pragma unroll
            for (int pl = 0; pl < 8; pl++)
                v += p[pl * B * D];
            smd[bb][tid] = v * inv;
        }
    }
    __syncthreads();

    float u0 = 0.f, u1 = 0.f;
    #pragma unroll
    for (int d = 0; d < 32; d++) {
        const int di = dg * 32 + d;
        u0 = fmaf(smd[0][di], w[d], u0);
        u1 = fmaf(smd[1][di], w[d], u1);
    }

    __shared__ float su[2][512];
    su[0][tid] = u0;
    su[1][tid] = u1;
    __syncthreads();

    // 64 results (2 batches x 32 n), each a 16-way partial sum.
    if (tid < 64) {
        const int bb = tid >> 5;      // batch within pair
        const int nn = tid & 31;
        float t = 0.f;
        #pragma unroll
        for (int g = 0; g < 16; g++)
            t += su[bb][g * 32 + nn];
        float bv = bias[nt * 32 + nn];
        out[(b0 + bb) * NN + nt * 32 + nn] =
            0.5f * (fmaxf(t + bv, 0.f) + fmaxf(bv - t, 0.f));
    }
}

extern "C" void kernel_launch(void* const* d_in, const int* in_sizes, int n_in,
                              void* d_out, int out_size)
{
    const float* gi   = (const float*)d_in[0];   // i     [B, L, D]
    const float* gj   = (const float*)d_in[1];   // j     [B, L, D]
    const float* W    = (const float*)d_in[2];   // W_agg [D, NN]
    const float* bias = (const float*)d_in[3];   // b_agg [NN]
    float* out = (float*)d_out;                  // [B, NN]

    mean_diff_kernel<<<1024, 256>>>(gi, gj, W);

    // PDL launch: gemv may begin (pre-wait phase) while kernel 1 drains.
    cudaLaunchConfig_t cfg = {};
    cfg.gridDim  = dim3(256, 1, 1);
    cfg.blockDim = dim3(512, 1, 1);
    cfg.dynamicSmemBytes = 0;
    cfg.stream = 0;   // legacy default stream (same as <<<>>> above)
    cudaLaunchAttribute attr[1];
    attr[0].id = cudaLaunchAttributeProgrammaticStreamSerialization;
    attr[0].val.programmaticStreamSerializationAllowed = 1;
    cfg.attrs = attr;
    cfg.numAttrs = 1;
    cudaLaunchKernelEx(&cfg, gemv_combine_kernel, W, bias, out);
}